// round 1
// baseline (speedup 1.0000x reference)
#include <cuda_runtime.h>
#include <math.h>

#define NN 8192
#define EPSF 1e-20f
#define NITER 32

// ---- device scratch (no allocations allowed) ----
__device__ float g_partials[32 * NN];
__device__ float g_b[NN], g_t[NN], g_Ap[NN], g_r[NN], g_p[NN], g_v[NN], g_qh[NN];
__device__ float g_rs[NITER + 2];
__device__ float g_dotpart[64];
__device__ float g_rspart[64];
__device__ float g_mpart[64 * 8];
__device__ float g_fftsum[8];

// y = H * x  (x = g_p if src_sel==0 else g_v; y = g_t / g_qh correspondingly)
__global__ void gemv_n_kernel(const float* __restrict__ H, int src_sel) {
    const float* xv = src_sel ? g_v : g_p;
    int row = blockIdx.x;
    const float4* h4 = reinterpret_cast<const float4*>(H + (size_t)row * NN);
    const float4* x4 = reinterpret_cast<const float4*>(xv);
    float acc = 0.f;
#pragma unroll
    for (int i = 0; i < 8; i++) {
        int idx = threadIdx.x + i * 256;
        float4 a = h4[idx];
        float4 b = x4[idx];
        acc += a.x * b.x + a.y * b.y + a.z * b.z + a.w * b.w;
    }
    __shared__ float sh[256];
    sh[threadIdx.x] = acc;
    __syncthreads();
    for (int s = 128; s > 0; s >>= 1) {
        if (threadIdx.x < s) sh[threadIdx.x] += sh[threadIdx.x + s];
        __syncthreads();
    }
    if (threadIdx.x == 0) {
        if (src_sel) g_qh[row] = sh[0];
        else         g_t[row]  = sh[0];
    }
}

// partial column sums for y = H^T * x  (x = g_t if use_t else xin)
// grid (32 colchunks, 32 rowchunks), 256 threads
__global__ void gemv_t_partial_kernel(const float* __restrict__ H,
                                      const float* __restrict__ xin, int use_t) {
    const float* xv = use_t ? g_t : xin;
    int col = blockIdx.x * 256 + threadIdx.x;
    int row0 = blockIdx.y * 256;
    __shared__ float xs[256];
    xs[threadIdx.x] = xv[row0 + threadIdx.x];
    __syncthreads();
    const float* Hp = H + (size_t)row0 * NN + col;
    float acc = 0.f;
#pragma unroll 8
    for (int r = 0; r < 256; r++) acc += Hp[(size_t)r * NN] * xs[r];
    g_partials[blockIdx.y * NN + col] = acc;
}

// reduce partials -> (g_b or g_Ap); emit dot partials of (self or p) with result
__global__ void reduce_t_kernel(int out_sel, int self_dot) {
    int j = blockIdx.x * 128 + threadIdx.x;
    float acc = 0.f;
#pragma unroll
    for (int c = 0; c < 32; c++) acc += g_partials[c * NN + j];
    if (out_sel) g_Ap[j] = acc;
    else         g_b[j]  = acc;
    float pv = self_dot ? acc : g_p[j];
    float d = pv * acc;
    __shared__ float sh4[4];
    for (int o = 16; o; o >>= 1) d += __shfl_down_sync(0xffffffffu, d, o);
    if ((threadIdx.x & 31) == 0) sh4[threadIdx.x >> 5] = d;
    __syncthreads();
    if (threadIdx.x == 0) g_dotpart[blockIdx.x] = sh4[0] + sh4[1] + sh4[2] + sh4[3];
}

__global__ void init_kernel() {
    int j = blockIdx.x * 128 + threadIdx.x;
    float b = g_b[j];
    g_v[j] = 0.f;
    g_r[j] = b;
    g_p[j] = b;
    if (blockIdx.x == 0 && threadIdx.x == 0) {
        float s = 0.f;
        for (int i = 0; i < 64; i++) s += g_dotpart[i];
        g_rs[0] = s;
    }
}

// alpha = rs/(pAp+eps); v += alpha p; r -= alpha Ap; emit partials of r.r
__global__ void axpy_kernel(int it) {
    float pAp = 0.f;
#pragma unroll
    for (int i = 0; i < 64; i++) pAp += g_dotpart[i];
    float alpha = g_rs[it] / (pAp + EPSF);
    int j = blockIdx.x * 128 + threadIdx.x;
    g_v[j] += alpha * g_p[j];
    float rn = g_r[j] - alpha * g_Ap[j];
    g_r[j] = rn;
    float d = rn * rn;
    __shared__ float sh4[4];
    for (int o = 16; o; o >>= 1) d += __shfl_down_sync(0xffffffffu, d, o);
    if ((threadIdx.x & 31) == 0) sh4[threadIdx.x >> 5] = d;
    __syncthreads();
    if (threadIdx.x == 0) g_rspart[blockIdx.x] = sh4[0] + sh4[1] + sh4[2] + sh4[3];
}

// rs_new = sum partials; beta = rs_new/(rs+eps); p = r + beta p; store rs_new
__global__ void pupdate_kernel(int it) {
    float rsn = 0.f;
#pragma unroll
    for (int i = 0; i < 64; i++) rsn += g_rspart[i];
    float beta = rsn / (g_rs[it] + EPSF);
    int j = blockIdx.x * 128 + threadIdx.x;
    g_p[j] = g_r[j] + beta * g_p[j];
    if (blockIdx.x == 0 && threadIdx.x == 0) g_rs[it + 1] = rsn;
}

// time-domain metric partials:
// s0=sum(qh-x)^2  s1=sum|qh-qt|  s2=sum(qh-qt)^2  s3=sum qt^2
// s4=sum|v-vt|    s5=sum(v-vt)^2 s6=sum vt^2
__global__ void metrics_partial_kernel(const float* __restrict__ x,
                                       const float* __restrict__ qt,
                                       const float* __restrict__ vt) {
    int j = blockIdx.x * 128 + threadIdx.x;
    float qh = g_qh[j], vv = g_v[j];
    float qtj = qt[j], vtj = vt[j];
    float d0 = qh - x[j];
    float d1 = qh - qtj;
    float d2 = vv - vtj;
    float vals[7] = { d0 * d0, fabsf(d1), d1 * d1, qtj * qtj,
                      fabsf(d2), d2 * d2, vtj * vtj };
    __shared__ float sh4[4];
#pragma unroll
    for (int s = 0; s < 7; s++) {
        float d = vals[s];
        for (int o = 16; o; o >>= 1) d += __shfl_down_sync(0xffffffffu, d, o);
        if ((threadIdx.x & 31) == 0) sh4[threadIdx.x >> 5] = d;
        __syncthreads();
        if (threadIdx.x == 0)
            g_mpart[blockIdx.x * 8 + s] = sh4[0] + sh4[1] + sh4[2] + sh4[3];
        __syncthreads();
    }
}

// 8192-pt real FFT via 4096-pt complex FFT (pack even/odd), per block.
// mode 0: qh - qt ; 1: qt ; 2: v - vt ; 3: vt
// emits g_fftsum[2m] = sum_k |X_k| , g_fftsum[2m+1] = sum_k |X_k|^2, k=0..4096
__global__ void fft_metrics_kernel(const float* __restrict__ qt,
                                   const float* __restrict__ vt) {
    __shared__ float2 Z[4096];
    __shared__ float red[1024];
    int mode = blockIdx.x;
    int tid = threadIdx.x;

    for (int n = tid; n < 4096; n += 1024) {
        int i0 = 2 * n, i1 = 2 * n + 1;
        float a, b;
        if (mode == 0)      { a = g_qh[i0] - qt[i0]; b = g_qh[i1] - qt[i1]; }
        else if (mode == 1) { a = qt[i0];            b = qt[i1]; }
        else if (mode == 2) { a = g_v[i0] - vt[i0];  b = g_v[i1] - vt[i1]; }
        else                { a = vt[i0];            b = vt[i1]; }
        int r = (int)(__brev((unsigned)n) >> 20);  // 12-bit reversal
        Z[r] = make_float2(a, b);
    }
    __syncthreads();

    for (int half = 1; half < 4096; half <<= 1) {
        for (int i = tid; i < 2048; i += 1024) {
            int pos = i & (half - 1);
            int idx1 = ((i ^ pos) << 1) | pos;
            int idx2 = idx1 + half;
            float s, c;
            sincospif((float)pos / (float)half, &s, &c);  // w = c - i s
            float2 z2 = Z[idx2];
            float2 t = make_float2(c * z2.x + s * z2.y, c * z2.y - s * z2.x);
            float2 z1 = Z[idx1];
            Z[idx2] = make_float2(z1.x - t.x, z1.y - t.y);
            Z[idx1] = make_float2(z1.x + t.x, z1.y + t.y);
        }
        __syncthreads();
    }

    float sabs = 0.f, ssq = 0.f;
    for (int k = tid; k <= 4096; k += 1024) {
        float2 Zk = Z[k & 4095];
        float2 Zm = Z[(4096 - k) & 4095];
        float2 Zmc = make_float2(Zm.x, -Zm.y);
        float2 Fe = make_float2(0.5f * (Zk.x + Zmc.x), 0.5f * (Zk.y + Zmc.y));
        float2 Fd = make_float2(Zk.x - Zmc.x, Zk.y - Zmc.y);
        float2 Fo = make_float2(0.5f * Fd.y, -0.5f * Fd.x);  // -i/2 * Fd
        float s, c;
        sincospif((float)k / 4096.0f, &s, &c);  // e^{-i*2pi*k/8192}
        float Xr = Fe.x + (c * Fo.x + s * Fo.y);
        float Xi = Fe.y + (c * Fo.y - s * Fo.x);
        float m2 = Xr * Xr + Xi * Xi;
        sabs += sqrtf(m2);
        ssq += m2;
    }
    red[tid] = sabs;
    __syncthreads();
    for (int s = 512; s > 0; s >>= 1) {
        if (tid < s) red[tid] += red[tid + s];
        __syncthreads();
    }
    if (tid == 0) g_fftsum[2 * mode] = red[0];
    __syncthreads();
    red[tid] = ssq;
    __syncthreads();
    for (int s = 512; s > 0; s >>= 1) {
        if (tid < s) red[tid] += red[tid + s];
        __syncthreads();
    }
    if (tid == 0) g_fftsum[2 * mode + 1] = red[0];
}

__global__ void finalize_kernel(float* __restrict__ out, int out_size) {
    if (threadIdx.x != 0 || blockIdx.x != 0) return;
    float s[7];
    for (int k = 0; k < 7; k++) {
        float a = 0.f;
        for (int b = 0; b < 64; b++) a += g_mpart[b * 8 + k];
        s[k] = a;
    }
    float res[11];
    res[0]  = sqrtf(s[0]);                      // residual
    res[1]  = s[1] / (float)NN;                 // mae_target
    res[2]  = s[2] / (s[3] + EPSF);             // ce_target
    res[3]  = s[4] / (float)NN;                 // mae
    res[4]  = s[5] / (s[6] + EPSF);             // ce
    res[5]  = s[2] / (float)NN;                 // mse_v_t_target
    res[6]  = s[5] / (float)NN;                 // mse_v_t
    res[7]  = g_fftsum[0] / 4097.0f;            // mae_target_f
    res[8]  = g_fftsum[1] / (g_fftsum[3] + EPSF); // ce_target_f
    res[9]  = g_fftsum[4] / 4097.0f;            // mae_f
    res[10] = g_fftsum[5] / (g_fftsum[7] + EPSF); // ce_f
    for (int k = 0; k < 11; k++)
        if (NN + k < out_size) out[NN + k] = res[k];
}

__global__ void copy_v_kernel(float* __restrict__ out, int out_size) {
    int j = blockIdx.x * 128 + threadIdx.x;
    if (j >= out_size) return;
    if (j < NN) out[j] = g_v[j];
    else if (j >= NN + 11) out[j] = 0.f;  // defensive: clear any extra slots
}

extern "C" void kernel_launch(void* const* d_in, const int* in_sizes, int n_in,
                              void* d_out, int out_size) {
    const float* H = nullptr;
    const float* x = nullptr;
    const float* vt = nullptr;
    const float* qt = nullptr;
    int vecseen = 0;
    for (int i = 0; i < n_in; i++) {
        if (in_sizes[i] == NN * NN) {
            H = (const float*)d_in[i];
        } else if (in_sizes[i] == NN) {
            if (vecseen == 0)      x  = (const float*)d_in[i];
            else if (vecseen == 1) vt = (const float*)d_in[i];
            else if (vecseen == 2) qt = (const float*)d_in[i];
            vecseen++;
        }
    }
    float* out = (float*)d_out;
    dim3 tgrid(32, 32);

    // b = H^T x ; r = p = b ; rs0 = b.b ; v = 0
    gemv_t_partial_kernel<<<tgrid, 256>>>(H, x, 0);
    reduce_t_kernel<<<64, 128>>>(0, 1);
    init_kernel<<<64, 128>>>();

    for (int it = 0; it < NITER; it++) {
        gemv_n_kernel<<<NN, 256>>>(H, 0);          // t = H p
        gemv_t_partial_kernel<<<tgrid, 256>>>(H, nullptr, 1);  // partials of H^T t
        reduce_t_kernel<<<64, 128>>>(1, 0);        // Ap + p.Ap partials
        axpy_kernel<<<64, 128>>>(it);              // alpha; v,r update; r.r partials
        pupdate_kernel<<<64, 128>>>(it);           // beta; p update; rs store
    }

    gemv_n_kernel<<<NN, 256>>>(H, 1);              // q_hat = H v
    metrics_partial_kernel<<<64, 128>>>(x, qt, vt);
    fft_metrics_kernel<<<4, 1024>>>(qt, vt);
    finalize_kernel<<<1, 32>>>(out, out_size);
    {
        int nblk = (out_size + 127) / 128;
        if (nblk < 1) nblk = 1;
        copy_v_kernel<<<nblk, 128>>>(out, out_size);
    }
}

// round 2
// speedup vs baseline: 1.0224x; 1.0224x over previous
#include <cuda_runtime.h>
#include <math.h>

#define NN 8192
#define EPSF 1e-20f
#define NITER 32

// ---- device scratch (no allocations allowed) ----
__device__ float g_partials[64 * NN];        // 2 MB: 64 row-chunks of column partials
__device__ float g_b[NN], g_t[NN], g_Ap[NN], g_r[NN], g_p[NN], g_v[NN], g_qh[NN];
__device__ float g_rs[NITER + 2];
__device__ float g_mpart[64 * 8];
__device__ float g_fftsum[8];

// ---------------------------------------------------------------------------
// t/qh = H * (p or v) : one block per row, 256 threads, float4, shfl reduce
// ---------------------------------------------------------------------------
__global__ __launch_bounds__(256) void gemv_n_kernel(const float* __restrict__ H,
                                                     int src_sel) {
    const float* xv = src_sel ? g_v : g_p;
    int row = blockIdx.x;
    const float4* h4 = reinterpret_cast<const float4*>(H + (size_t)row * NN);
    const float4* x4 = reinterpret_cast<const float4*>(xv);
    float acc0 = 0.f, acc1 = 0.f;
#pragma unroll
    for (int i = 0; i < 8; i += 2) {
        int i0 = threadIdx.x + i * 256;
        int i1 = threadIdx.x + (i + 1) * 256;
        float4 a0 = h4[i0], b0 = x4[i0];
        float4 a1 = h4[i1], b1 = x4[i1];
        acc0 += a0.x * b0.x + a0.y * b0.y + a0.z * b0.z + a0.w * b0.w;
        acc1 += a1.x * b1.x + a1.y * b1.y + a1.z * b1.z + a1.w * b1.w;
    }
    float acc = acc0 + acc1;
    for (int o = 16; o; o >>= 1) acc += __shfl_down_sync(0xffffffffu, acc, o);
    __shared__ float sh[8];
    if ((threadIdx.x & 31) == 0) sh[threadIdx.x >> 5] = acc;
    __syncthreads();
    if (threadIdx.x < 8) {
        float s = sh[threadIdx.x];
        s += __shfl_down_sync(0xffu, s, 4);
        s += __shfl_down_sync(0xffu, s, 2);
        s += __shfl_down_sync(0xffu, s, 1);
        if (threadIdx.x == 0) {
            if (src_sel) g_qh[row] = s;
            else         g_t[row]  = s;
        }
    }
}

// ---------------------------------------------------------------------------
// partial column sums of H^T * x. float4 per thread across columns.
// grid (8 col-chunks, 64 row-chunks), 256 threads. Row chunks REVERSED so the
// first-launched blocks read the rows most recently resident in L2 from the
// preceding gemv_n pass.
// ---------------------------------------------------------------------------
__global__ __launch_bounds__(256) void gemv_t_partial_kernel(
    const float* __restrict__ H, const float* __restrict__ xin, int use_t) {
    const float* xv = use_t ? g_t : xin;
    int col4 = blockIdx.x * 256 + threadIdx.x;    // float4 column index (0..2047)
    int ry = 63 - blockIdx.y;                     // reversed row chunk
    int row0 = ry * 128;
    __shared__ float xs[128];
    if (threadIdx.x < 128) xs[threadIdx.x] = xv[row0 + threadIdx.x];
    __syncthreads();
    const float4* Hp = reinterpret_cast<const float4*>(H) + (size_t)row0 * 2048 + col4;
    float4 acc = make_float4(0.f, 0.f, 0.f, 0.f);
#pragma unroll 4
    for (int r = 0; r < 128; r++) {
        float4 h = Hp[(size_t)r * 2048];
        float s = xs[r];
        acc.x += h.x * s; acc.y += h.y * s; acc.z += h.z * s; acc.w += h.w * s;
    }
    reinterpret_cast<float4*>(g_partials)[(size_t)ry * 2048 + col4] = acc;
}

// reduce 64 partial slabs -> g_b (out_sel=0) or g_Ap (out_sel=1)
__global__ __launch_bounds__(256) void reduce_t_kernel(int out_sel) {
    int j = blockIdx.x * 256 + threadIdx.x;       // float4 index (2048 total)
    const float4* part = reinterpret_cast<const float4*>(g_partials);
    float4 acc = make_float4(0.f, 0.f, 0.f, 0.f);
#pragma unroll
    for (int c = 0; c < 64; c++) {
        float4 v = part[(size_t)c * 2048 + j];
        acc.x += v.x; acc.y += v.y; acc.z += v.z; acc.w += v.w;
    }
    reinterpret_cast<float4*>(out_sel ? g_Ap : g_b)[j] = acc;
}

// ---- block-wide fp32 sum helper (1024 threads) ----
__device__ __forceinline__ float block_sum_1024(float v, float* sh32) {
    for (int o = 16; o; o >>= 1) v += __shfl_down_sync(0xffffffffu, v, o);
    if ((threadIdx.x & 31) == 0) sh32[threadIdx.x >> 5] = v;
    __syncthreads();
    float s = 0.f;
    if (threadIdx.x == 0) {
#pragma unroll
        for (int i = 0; i < 32; i++) s += sh32[i];
        sh32[0] = s;
    }
    __syncthreads();
    s = sh32[0];
    __syncthreads();
    return s;
}

// v=0 ; r=p=b ; rs0 = b.b   (single block, 1024 threads, float4 x2)
__global__ __launch_bounds__(1024) void init_fused_kernel() {
    __shared__ float sh32[32];
    float part = 0.f;
#pragma unroll
    for (int i = 0; i < 2; i++) {
        int j = threadIdx.x + i * 1024;           // float4 index
        float4 b = reinterpret_cast<const float4*>(g_b)[j];
        reinterpret_cast<float4*>(g_r)[j] = b;
        reinterpret_cast<float4*>(g_p)[j] = b;
        reinterpret_cast<float4*>(g_v)[j] = make_float4(0.f, 0.f, 0.f, 0.f);
        part += b.x * b.x + b.y * b.y + b.z * b.z + b.w * b.w;
    }
    float rs = block_sum_1024(part, sh32);
    if (threadIdx.x == 0) g_rs[0] = rs;
}

// One fused CG scalar+vector step (single block, 1024 threads):
// tt = ||t||^2 (= p.Ap) ; alpha = rs/(tt+eps) ; v += alpha p ; r -= alpha Ap ;
// rsn = ||r||^2 ; beta = rsn/(rs+eps) ; p = r + beta p ; rs <- rsn
__global__ __launch_bounds__(1024) void cg_fused_kernel(int it) {
    __shared__ float sh32[32];
    // tt
    float ttp = 0.f;
#pragma unroll
    for (int i = 0; i < 2; i++) {
        int j = threadIdx.x + i * 1024;
        float4 t = reinterpret_cast<const float4*>(g_t)[j];
        ttp += t.x * t.x + t.y * t.y + t.z * t.z + t.w * t.w;
    }
    float tt = block_sum_1024(ttp, sh32);
    float rs = g_rs[it];
    float alpha = rs / (tt + EPSF);

    float4 preg[2], rreg[2];
    float rsp = 0.f;
#pragma unroll
    for (int i = 0; i < 2; i++) {
        int j = threadIdx.x + i * 1024;
        float4 p  = reinterpret_cast<const float4*>(g_p)[j];
        float4 ap = reinterpret_cast<const float4*>(g_Ap)[j];
        float4 r  = reinterpret_cast<const float4*>(g_r)[j];
        float4 v  = reinterpret_cast<const float4*>(g_v)[j];
        v.x += alpha * p.x; v.y += alpha * p.y; v.z += alpha * p.z; v.w += alpha * p.w;
        r.x -= alpha * ap.x; r.y -= alpha * ap.y; r.z -= alpha * ap.z; r.w -= alpha * ap.w;
        reinterpret_cast<float4*>(g_v)[j] = v;
        reinterpret_cast<float4*>(g_r)[j] = r;
        preg[i] = p; rreg[i] = r;
        rsp += r.x * r.x + r.y * r.y + r.z * r.z + r.w * r.w;
    }
    float rsn = block_sum_1024(rsp, sh32);
    float beta = rsn / (rs + EPSF);
#pragma unroll
    for (int i = 0; i < 2; i++) {
        int j = threadIdx.x + i * 1024;
        float4 p = preg[i], r = rreg[i];
        p.x = r.x + beta * p.x; p.y = r.y + beta * p.y;
        p.z = r.z + beta * p.z; p.w = r.w + beta * p.w;
        reinterpret_cast<float4*>(g_p)[j] = p;
    }
    if (threadIdx.x == 0) g_rs[it + 1] = rsn;
}

// time-domain metric partials (unchanged semantics):
// s0=sum(qh-x)^2 s1=sum|qh-qt| s2=sum(qh-qt)^2 s3=sum qt^2
// s4=sum|v-vt|   s5=sum(v-vt)^2 s6=sum vt^2
__global__ void metrics_partial_kernel(const float* __restrict__ x,
                                       const float* __restrict__ qt,
                                       const float* __restrict__ vt) {
    int j = blockIdx.x * 128 + threadIdx.x;
    float qh = g_qh[j], vv = g_v[j];
    float qtj = qt[j], vtj = vt[j];
    float d0 = qh - x[j];
    float d1 = qh - qtj;
    float d2 = vv - vtj;
    float vals[7] = { d0 * d0, fabsf(d1), d1 * d1, qtj * qtj,
                      fabsf(d2), d2 * d2, vtj * vtj };
    __shared__ float sh4[4];
#pragma unroll
    for (int s = 0; s < 7; s++) {
        float d = vals[s];
        for (int o = 16; o; o >>= 1) d += __shfl_down_sync(0xffffffffu, d, o);
        if ((threadIdx.x & 31) == 0) sh4[threadIdx.x >> 5] = d;
        __syncthreads();
        if (threadIdx.x == 0)
            g_mpart[blockIdx.x * 8 + s] = sh4[0] + sh4[1] + sh4[2] + sh4[3];
        __syncthreads();
    }
}

// 8192-pt real FFT via 4096-pt complex FFT (pack even/odd), per block.
// mode 0: qh - qt ; 1: qt ; 2: v - vt ; 3: vt
// emits g_fftsum[2m] = sum_k |X_k|, g_fftsum[2m+1] = sum_k |X_k|^2, k=0..4096
__global__ void fft_metrics_kernel(const float* __restrict__ qt,
                                   const float* __restrict__ vt) {
    __shared__ float2 Z[4096];
    __shared__ float red[1024];
    int mode = blockIdx.x;
    int tid = threadIdx.x;

    for (int n = tid; n < 4096; n += 1024) {
        int i0 = 2 * n, i1 = 2 * n + 1;
        float a, b;
        if (mode == 0)      { a = g_qh[i0] - qt[i0]; b = g_qh[i1] - qt[i1]; }
        else if (mode == 1) { a = qt[i0];            b = qt[i1]; }
        else if (mode == 2) { a = g_v[i0] - vt[i0];  b = g_v[i1] - vt[i1]; }
        else                { a = vt[i0];            b = vt[i1]; }
        int r = (int)(__brev((unsigned)n) >> 20);  // 12-bit reversal
        Z[r] = make_float2(a, b);
    }
    __syncthreads();

    for (int half = 1; half < 4096; half <<= 1) {
        for (int i = tid; i < 2048; i += 1024) {
            int pos = i & (half - 1);
            int idx1 = ((i ^ pos) << 1) | pos;
            int idx2 = idx1 + half;
            float s, c;
            sincospif((float)pos / (float)half, &s, &c);  // w = c - i s
            float2 z2 = Z[idx2];
            float2 t = make_float2(c * z2.x + s * z2.y, c * z2.y - s * z2.x);
            float2 z1 = Z[idx1];
            Z[idx2] = make_float2(z1.x - t.x, z1.y - t.y);
            Z[idx1] = make_float2(z1.x + t.x, z1.y + t.y);
        }
        __syncthreads();
    }

    float sabs = 0.f, ssq = 0.f;
    for (int k = tid; k <= 4096; k += 1024) {
        float2 Zk = Z[k & 4095];
        float2 Zm = Z[(4096 - k) & 4095];
        float2 Zmc = make_float2(Zm.x, -Zm.y);
        float2 Fe = make_float2(0.5f * (Zk.x + Zmc.x), 0.5f * (Zk.y + Zmc.y));
        float2 Fd = make_float2(Zk.x - Zmc.x, Zk.y - Zmc.y);
        float2 Fo = make_float2(0.5f * Fd.y, -0.5f * Fd.x);  // -i/2 * Fd
        float s, c;
        sincospif((float)k / 4096.0f, &s, &c);  // e^{-i*2pi*k/8192}
        float Xr = Fe.x + (c * Fo.x + s * Fo.y);
        float Xi = Fe.y + (c * Fo.y - s * Fo.x);
        float m2 = Xr * Xr + Xi * Xi;
        sabs += sqrtf(m2);
        ssq += m2;
    }
    red[tid] = sabs;
    __syncthreads();
    for (int s = 512; s > 0; s >>= 1) {
        if (tid < s) red[tid] += red[tid + s];
        __syncthreads();
    }
    if (tid == 0) g_fftsum[2 * mode] = red[0];
    __syncthreads();
    red[tid] = ssq;
    __syncthreads();
    for (int s = 512; s > 0; s >>= 1) {
        if (tid < s) red[tid] += red[tid + s];
        __syncthreads();
    }
    if (tid == 0) g_fftsum[2 * mode + 1] = red[0];
}

__global__ void finalize_kernel(float* __restrict__ out, int out_size) {
    if (threadIdx.x != 0 || blockIdx.x != 0) return;
    float s[7];
    for (int k = 0; k < 7; k++) {
        float a = 0.f;
        for (int b = 0; b < 64; b++) a += g_mpart[b * 8 + k];
        s[k] = a;
    }
    float res[11];
    res[0]  = sqrtf(s[0]);                        // residual
    res[1]  = s[1] / (float)NN;                   // mae_target
    res[2]  = s[2] / (s[3] + EPSF);               // ce_target
    res[3]  = s[4] / (float)NN;                   // mae
    res[4]  = s[5] / (s[6] + EPSF);               // ce
    res[5]  = s[2] / (float)NN;                   // mse_v_t_target
    res[6]  = s[5] / (float)NN;                   // mse_v_t
    res[7]  = g_fftsum[0] / 4097.0f;              // mae_target_f
    res[8]  = g_fftsum[1] / (g_fftsum[3] + EPSF); // ce_target_f
    res[9]  = g_fftsum[4] / 4097.0f;              // mae_f
    res[10] = g_fftsum[5] / (g_fftsum[7] + EPSF); // ce_f
    for (int k = 0; k < 11; k++)
        if (NN + k < out_size) out[NN + k] = res[k];
}

__global__ void copy_v_kernel(float* __restrict__ out, int out_size) {
    int j = blockIdx.x * 128 + threadIdx.x;
    if (j >= out_size) return;
    if (j < NN) out[j] = g_v[j];
    else if (j >= NN + 11) out[j] = 0.f;
}

extern "C" void kernel_launch(void* const* d_in, const int* in_sizes, int n_in,
                              void* d_out, int out_size) {
    const float* H = nullptr;
    const float* x = nullptr;
    const float* vt = nullptr;
    const float* qt = nullptr;
    int vecseen = 0;
    for (int i = 0; i < n_in; i++) {
        if (in_sizes[i] == NN * NN) {
            H = (const float*)d_in[i];
        } else if (in_sizes[i] == NN) {
            if (vecseen == 0)      x  = (const float*)d_in[i];
            else if (vecseen == 1) vt = (const float*)d_in[i];
            else if (vecseen == 2) qt = (const float*)d_in[i];
            vecseen++;
        }
    }
    float* out = (float*)d_out;
    dim3 tgrid(8, 64);

    // b = H^T x ; v=0 ; r=p=b ; rs0=b.b
    gemv_t_partial_kernel<<<tgrid, 256>>>(H, x, 0);
    reduce_t_kernel<<<8, 256>>>(0);
    init_fused_kernel<<<1, 1024>>>();

    for (int it = 0; it < NITER; it++) {
        gemv_n_kernel<<<NN, 256>>>(H, 0);                      // t = H p
        gemv_t_partial_kernel<<<tgrid, 256>>>(H, nullptr, 1);  // partials of H^T t
        reduce_t_kernel<<<8, 256>>>(1);                        // Ap
        cg_fused_kernel<<<1, 1024>>>(it);                      // alpha/beta + updates
    }

    gemv_n_kernel<<<NN, 256>>>(H, 1);                          // q_hat = H v
    metrics_partial_kernel<<<64, 128>>>(x, qt, vt);
    fft_metrics_kernel<<<4, 1024>>>(qt, vt);
    finalize_kernel<<<1, 32>>>(out, out_size);
    {
        int nblk = (out_size + 127) / 128;
        if (nblk < 1) nblk = 1;
        copy_v_kernel<<<nblk, 128>>>(out, out_size);
    }
}

// round 3
// speedup vs baseline: 1.2444x; 1.2172x over previous
#include <cuda_runtime.h>
#include <math.h>

#define NN 8192
#define EPSF 1e-20f
#define NITER 32
#define GRIDF 296           // 2 CTAs/SM x 148 SMs, single wave

// ---- device scratch (no allocations allowed) ----
__device__ float g_slab[GRIDF * NN];          // 9.5 MB partial slabs (also reused by setup: 64*NN)
__device__ float g_partred[8 * NN];           // stage-2 reduced partials (8 groups)
__device__ float g_ttpart[GRIDF];             // per-CTA sum of t_r^2  (= p.Ap partials)
__device__ float g_b[NN], g_r[NN], g_p[NN], g_v[NN], g_qh[NN];
__device__ float g_rs[NITER + 2];
__device__ float g_mpart[64 * 8];
__device__ float g_fftsum[8];

// ---------------------------------------------------------------------------
// Fused normal-equations operator: ONE pass over H computes per-CTA partials of
// Ap = H^T (H p) and tt = ||H p||^2 = p.Ap.
// Per row: stage row in registers, dot with p (smem), block-reduce -> t_r,
// then Ap_local += t_r * row (thread owns the columns it loaded).
// ---------------------------------------------------------------------------
__global__ __launch_bounds__(256) void normal_fused_kernel(const float* __restrict__ H) {
    __shared__ float4 psh[2048];     // p, 32 KB
    __shared__ float sw[2][8];
    int tid = threadIdx.x;
    const float4* p4 = reinterpret_cast<const float4*>(g_p);
    for (int i = tid; i < 2048; i += 256) psh[i] = p4[i];
    __syncthreads();

    int bid = blockIdx.x;
    int row0, nrows;
    if (bid < 200) { row0 = bid * 28; nrows = 28; }
    else           { row0 = 5600 + (bid - 200) * 27; nrows = 27; }

    float4 apa[8];
#pragma unroll
    for (int i = 0; i < 8; i++) apa[i] = make_float4(0.f, 0.f, 0.f, 0.f);
    float tta = 0.f;

    for (int r = 0; r < nrows; r++) {
        const float4* h4 = reinterpret_cast<const float4*>(H) + (size_t)(row0 + r) * 2048;
        float4 st[8];
        float d = 0.f;
#pragma unroll
        for (int i = 0; i < 8; i++) {
            int idx = tid + i * 256;
            float4 h = h4[idx];
            float4 pp = psh[idx];
            st[i] = h;
            d += h.x * pp.x + h.y * pp.y + h.z * pp.z + h.w * pp.w;
        }
        for (int o = 16; o; o >>= 1) d += __shfl_xor_sync(0xffffffffu, d, o);
        int buf = r & 1;
        if ((tid & 31) == 0) sw[buf][tid >> 5] = d;
        __syncthreads();
        float tr = sw[buf][0] + sw[buf][1] + sw[buf][2] + sw[buf][3]
                 + sw[buf][4] + sw[buf][5] + sw[buf][6] + sw[buf][7];
        if (tid == 0) tta += tr * tr;
#pragma unroll
        for (int i = 0; i < 8; i++) {
            apa[i].x += tr * st[i].x; apa[i].y += tr * st[i].y;
            apa[i].z += tr * st[i].z; apa[i].w += tr * st[i].w;
        }
    }
    float4* slab4 = reinterpret_cast<float4*>(g_slab) + (size_t)bid * 2048;
#pragma unroll
    for (int i = 0; i < 8; i++) slab4[tid + i * 256] = apa[i];
    if (tid == 0) g_ttpart[bid] = tta;
}

// stage-2 slab reduce: 296 slabs -> 8 group partials. grid (8 colblocks, 8 groups)
__global__ __launch_bounds__(256) void reduce_slab_kernel() {
    int j = blockIdx.x * 256 + threadIdx.x;       // float4 column (0..2047)
    int g = blockIdx.y;                           // group 0..7 (37 slabs each)
    const float4* s4 = reinterpret_cast<const float4*>(g_slab);
    float4 acc = make_float4(0.f, 0.f, 0.f, 0.f);
    int c0 = g * 37;
#pragma unroll 4
    for (int c = 0; c < 37; c++) {
        float4 v = s4[(size_t)(c0 + c) * 2048 + j];
        acc.x += v.x; acc.y += v.y; acc.z += v.z; acc.w += v.w;
    }
    reinterpret_cast<float4*>(g_partred)[(size_t)g * 2048 + j] = acc;
}

// ---------------------------------------------------------------------------
// qh = H v : one block per row (final pass only)
// ---------------------------------------------------------------------------
__global__ __launch_bounds__(256) void gemv_n_kernel(const float* __restrict__ H) {
    int row = blockIdx.x;
    const float4* h4 = reinterpret_cast<const float4*>(H + (size_t)row * NN);
    const float4* x4 = reinterpret_cast<const float4*>(g_v);
    float acc = 0.f;
#pragma unroll
    for (int i = 0; i < 8; i++) {
        int idx = threadIdx.x + i * 256;
        float4 a = h4[idx], b = x4[idx];
        acc += a.x * b.x + a.y * b.y + a.z * b.z + a.w * b.w;
    }
    for (int o = 16; o; o >>= 1) acc += __shfl_down_sync(0xffffffffu, acc, o);
    __shared__ float sh[8];
    if ((threadIdx.x & 31) == 0) sh[threadIdx.x >> 5] = acc;
    __syncthreads();
    if (threadIdx.x == 0) {
        g_qh[row] = sh[0] + sh[1] + sh[2] + sh[3] + sh[4] + sh[5] + sh[6] + sh[7];
    }
}

// setup: partial column sums of b = H^T x. grid (8 colchunks, 64 rowchunks).
__global__ __launch_bounds__(256) void gemv_t_partial_kernel(
    const float* __restrict__ H, const float* __restrict__ xin) {
    int col4 = blockIdx.x * 256 + threadIdx.x;
    int row0 = blockIdx.y * 128;
    __shared__ float xs[128];
    if (threadIdx.x < 128) xs[threadIdx.x] = xin[row0 + threadIdx.x];
    __syncthreads();
    const float4* Hp = reinterpret_cast<const float4*>(H) + (size_t)row0 * 2048 + col4;
    float4 acc = make_float4(0.f, 0.f, 0.f, 0.f);
#pragma unroll 4
    for (int r = 0; r < 128; r++) {
        float4 h = Hp[(size_t)r * 2048];
        float s = xs[r];
        acc.x += h.x * s; acc.y += h.y * s; acc.z += h.z * s; acc.w += h.w * s;
    }
    reinterpret_cast<float4*>(g_slab)[(size_t)blockIdx.y * 2048 + col4] = acc;
}

// setup reduce: 64 slabs -> g_b
__global__ __launch_bounds__(256) void reduce_b64_kernel() {
    int j = blockIdx.x * 256 + threadIdx.x;
    const float4* part = reinterpret_cast<const float4*>(g_slab);
    float4 acc = make_float4(0.f, 0.f, 0.f, 0.f);
#pragma unroll
    for (int c = 0; c < 64; c++) {
        float4 v = part[(size_t)c * 2048 + j];
        acc.x += v.x; acc.y += v.y; acc.z += v.z; acc.w += v.w;
    }
    reinterpret_cast<float4*>(g_b)[j] = acc;
}

// ---- block-wide fp32 sum helper (1024 threads) ----
__device__ __forceinline__ float block_sum_1024(float v, float* sh32) {
    for (int o = 16; o; o >>= 1) v += __shfl_down_sync(0xffffffffu, v, o);
    if ((threadIdx.x & 31) == 0) sh32[threadIdx.x >> 5] = v;
    __syncthreads();
    float s = 0.f;
    if (threadIdx.x == 0) {
#pragma unroll
        for (int i = 0; i < 32; i++) s += sh32[i];
        sh32[0] = s;
    }
    __syncthreads();
    s = sh32[0];
    __syncthreads();
    return s;
}

// v=0 ; r=p=b ; rs0 = b.b   (single block, 1024 threads)
__global__ __launch_bounds__(1024) void init_fused_kernel() {
    __shared__ float sh32[32];
    float part = 0.f;
#pragma unroll
    for (int i = 0; i < 2; i++) {
        int j = threadIdx.x + i * 1024;
        float4 b = reinterpret_cast<const float4*>(g_b)[j];
        reinterpret_cast<float4*>(g_r)[j] = b;
        reinterpret_cast<float4*>(g_p)[j] = b;
        reinterpret_cast<float4*>(g_v)[j] = make_float4(0.f, 0.f, 0.f, 0.f);
        part += b.x * b.x + b.y * b.y + b.z * b.z + b.w * b.w;
    }
    float rs = block_sum_1024(part, sh32);
    if (threadIdx.x == 0) g_rs[0] = rs;
}

// Fused CG step: tt = sum ttpart ; alpha = rs/(tt+eps) ; Ap from 8 group
// partials ; v += alpha p ; r -= alpha Ap ; rsn=||r||^2 ; beta ; p = r+beta p
__global__ __launch_bounds__(1024) void cg_fused_kernel(int it) {
    __shared__ float sh32[32];
    float ttp = 0.f;
    for (int i = threadIdx.x; i < GRIDF; i += 1024) ttp += g_ttpart[i];
    float tt = block_sum_1024(ttp, sh32);
    float rs = g_rs[it];
    float alpha = rs / (tt + EPSF);

    const float4* pr4 = reinterpret_cast<const float4*>(g_partred);
    float4 preg[2], rreg[2];
    float rsp = 0.f;
#pragma unroll
    for (int i = 0; i < 2; i++) {
        int j = threadIdx.x + i * 1024;
        float4 ap = make_float4(0.f, 0.f, 0.f, 0.f);
#pragma unroll
        for (int g = 0; g < 8; g++) {
            float4 v = pr4[(size_t)g * 2048 + j];
            ap.x += v.x; ap.y += v.y; ap.z += v.z; ap.w += v.w;
        }
        float4 p = reinterpret_cast<const float4*>(g_p)[j];
        float4 r = reinterpret_cast<const float4*>(g_r)[j];
        float4 v = reinterpret_cast<const float4*>(g_v)[j];
        v.x += alpha * p.x; v.y += alpha * p.y; v.z += alpha * p.z; v.w += alpha * p.w;
        r.x -= alpha * ap.x; r.y -= alpha * ap.y; r.z -= alpha * ap.z; r.w -= alpha * ap.w;
        reinterpret_cast<float4*>(g_v)[j] = v;
        reinterpret_cast<float4*>(g_r)[j] = r;
        preg[i] = p; rreg[i] = r;
        rsp += r.x * r.x + r.y * r.y + r.z * r.z + r.w * r.w;
    }
    float rsn = block_sum_1024(rsp, sh32);
    float beta = rsn / (rs + EPSF);
#pragma unroll
    for (int i = 0; i < 2; i++) {
        int j = threadIdx.x + i * 1024;
        float4 p = preg[i], r = rreg[i];
        p.x = r.x + beta * p.x; p.y = r.y + beta * p.y;
        p.z = r.z + beta * p.z; p.w = r.w + beta * p.w;
        reinterpret_cast<float4*>(g_p)[j] = p;
    }
    if (threadIdx.x == 0) g_rs[it + 1] = rsn;
}

// time-domain metric partials:
// s0=sum(qh-x)^2 s1=sum|qh-qt| s2=sum(qh-qt)^2 s3=sum qt^2
// s4=sum|v-vt|   s5=sum(v-vt)^2 s6=sum vt^2
__global__ void metrics_partial_kernel(const float* __restrict__ x,
                                       const float* __restrict__ qt,
                                       const float* __restrict__ vt) {
    int j = blockIdx.x * 128 + threadIdx.x;
    float qh = g_qh[j], vv = g_v[j];
    float qtj = qt[j], vtj = vt[j];
    float d0 = qh - x[j];
    float d1 = qh - qtj;
    float d2 = vv - vtj;
    float vals[7] = { d0 * d0, fabsf(d1), d1 * d1, qtj * qtj,
                      fabsf(d2), d2 * d2, vtj * vtj };
    __shared__ float sh4[4];
#pragma unroll
    for (int s = 0; s < 7; s++) {
        float d = vals[s];
        for (int o = 16; o; o >>= 1) d += __shfl_down_sync(0xffffffffu, d, o);
        if ((threadIdx.x & 31) == 0) sh4[threadIdx.x >> 5] = d;
        __syncthreads();
        if (threadIdx.x == 0)
            g_mpart[blockIdx.x * 8 + s] = sh4[0] + sh4[1] + sh4[2] + sh4[3];
        __syncthreads();
    }
}

// 8192-pt real FFT via 4096-pt complex FFT (pack even/odd), per block.
// mode 0: qh - qt ; 1: qt ; 2: v - vt ; 3: vt
__global__ void fft_metrics_kernel(const float* __restrict__ qt,
                                   const float* __restrict__ vt) {
    __shared__ float2 Z[4096];
    __shared__ float red[1024];
    int mode = blockIdx.x;
    int tid = threadIdx.x;

    for (int n = tid; n < 4096; n += 1024) {
        int i0 = 2 * n, i1 = 2 * n + 1;
        float a, b;
        if (mode == 0)      { a = g_qh[i0] - qt[i0]; b = g_qh[i1] - qt[i1]; }
        else if (mode == 1) { a = qt[i0];            b = qt[i1]; }
        else if (mode == 2) { a = g_v[i0] - vt[i0];  b = g_v[i1] - vt[i1]; }
        else                { a = vt[i0];            b = vt[i1]; }
        int r = (int)(__brev((unsigned)n) >> 20);  // 12-bit reversal
        Z[r] = make_float2(a, b);
    }
    __syncthreads();

    for (int half = 1; half < 4096; half <<= 1) {
        for (int i = tid; i < 2048; i += 1024) {
            int pos = i & (half - 1);
            int idx1 = ((i ^ pos) << 1) | pos;
            int idx2 = idx1 + half;
            float s, c;
            sincospif((float)pos / (float)half, &s, &c);  // w = c - i s
            float2 z2 = Z[idx2];
            float2 t = make_float2(c * z2.x + s * z2.y, c * z2.y - s * z2.x);
            float2 z1 = Z[idx1];
            Z[idx2] = make_float2(z1.x - t.x, z1.y - t.y);
            Z[idx1] = make_float2(z1.x + t.x, z1.y + t.y);
        }
        __syncthreads();
    }

    float sabs = 0.f, ssq = 0.f;
    for (int k = tid; k <= 4096; k += 1024) {
        float2 Zk = Z[k & 4095];
        float2 Zm = Z[(4096 - k) & 4095];
        float2 Zmc = make_float2(Zm.x, -Zm.y);
        float2 Fe = make_float2(0.5f * (Zk.x + Zmc.x), 0.5f * (Zk.y + Zmc.y));
        float2 Fd = make_float2(Zk.x - Zmc.x, Zk.y - Zmc.y);
        float2 Fo = make_float2(0.5f * Fd.y, -0.5f * Fd.x);  // -i/2 * Fd
        float s, c;
        sincospif((float)k / 4096.0f, &s, &c);  // e^{-i*2pi*k/8192}
        float Xr = Fe.x + (c * Fo.x + s * Fo.y);
        float Xi = Fe.y + (c * Fo.y - s * Fo.x);
        float m2 = Xr * Xr + Xi * Xi;
        sabs += sqrtf(m2);
        ssq += m2;
    }
    red[tid] = sabs;
    __syncthreads();
    for (int s = 512; s > 0; s >>= 1) {
        if (tid < s) red[tid] += red[tid + s];
        __syncthreads();
    }
    if (tid == 0) g_fftsum[2 * mode] = red[0];
    __syncthreads();
    red[tid] = ssq;
    __syncthreads();
    for (int s = 512; s > 0; s >>= 1) {
        if (tid < s) red[tid] += red[tid + s];
        __syncthreads();
    }
    if (tid == 0) g_fftsum[2 * mode + 1] = red[0];
}

__global__ void finalize_kernel(float* __restrict__ out, int out_size) {
    if (threadIdx.x != 0 || blockIdx.x != 0) return;
    float s[7];
    for (int k = 0; k < 7; k++) {
        float a = 0.f;
        for (int b = 0; b < 64; b++) a += g_mpart[b * 8 + k];
        s[k] = a;
    }
    float res[11];
    res[0]  = sqrtf(s[0]);                        // residual
    res[1]  = s[1] / (float)NN;                   // mae_target
    res[2]  = s[2] / (s[3] + EPSF);               // ce_target
    res[3]  = s[4] / (float)NN;                   // mae
    res[4]  = s[5] / (s[6] + EPSF);               // ce
    res[5]  = s[2] / (float)NN;                   // mse_v_t_target
    res[6]  = s[5] / (float)NN;                   // mse_v_t
    res[7]  = g_fftsum[0] / 4097.0f;              // mae_target_f
    res[8]  = g_fftsum[1] / (g_fftsum[3] + EPSF); // ce_target_f
    res[9]  = g_fftsum[4] / 4097.0f;              // mae_f
    res[10] = g_fftsum[5] / (g_fftsum[7] + EPSF); // ce_f
    for (int k = 0; k < 11; k++)
        if (NN + k < out_size) out[NN + k] = res[k];
}

__global__ void copy_v_kernel(float* __restrict__ out, int out_size) {
    int j = blockIdx.x * 128 + threadIdx.x;
    if (j >= out_size) return;
    if (j < NN) out[j] = g_v[j];
    else if (j >= NN + 11) out[j] = 0.f;
}

extern "C" void kernel_launch(void* const* d_in, const int* in_sizes, int n_in,
                              void* d_out, int out_size) {
    const float* H = nullptr;
    const float* x = nullptr;
    const float* vt = nullptr;
    const float* qt = nullptr;
    int vecseen = 0;
    for (int i = 0; i < n_in; i++) {
        if (in_sizes[i] == NN * NN) {
            H = (const float*)d_in[i];
        } else if (in_sizes[i] == NN) {
            if (vecseen == 0)      x  = (const float*)d_in[i];
            else if (vecseen == 1) vt = (const float*)d_in[i];
            else if (vecseen == 2) qt = (const float*)d_in[i];
            vecseen++;
        }
    }
    float* out = (float*)d_out;

    // b = H^T x ; v=0 ; r=p=b ; rs0=b.b
    gemv_t_partial_kernel<<<dim3(8, 64), 256>>>(H, x);
    reduce_b64_kernel<<<8, 256>>>();
    init_fused_kernel<<<1, 1024>>>();

    for (int it = 0; it < NITER; it++) {
        normal_fused_kernel<<<GRIDF, 256>>>(H);       // one pass: Ap partials + tt
        reduce_slab_kernel<<<dim3(8, 8), 256>>>();    // 296 -> 8 group partials
        cg_fused_kernel<<<1, 1024>>>(it);             // scalars + vector updates
    }

    gemv_n_kernel<<<NN, 256>>>(H);                    // q_hat = H v
    metrics_partial_kernel<<<64, 128>>>(x, qt, vt);
    fft_metrics_kernel<<<4, 1024>>>(qt, vt);
    finalize_kernel<<<1, 32>>>(out, out_size);
    {
        int nblk = (out_size + 127) / 128;
        if (nblk < 1) nblk = 1;
        copy_v_kernel<<<nblk, 128>>>(out, out_size);
    }
}

// round 4
// speedup vs baseline: 1.5069x; 1.2109x over previous
#include <cuda_runtime.h>
#include <math.h>

#define NN 8192
#define EPSF 1e-20f
#define NITER 32
#define GRIDF 296           // 2 CTAs/SM x 148 SMs, single wave

// ---- device scratch (no allocations allowed) ----
__device__ float g_slab[GRIDF * NN];          // 9.5 MB partial slabs (setup reuses first 64 slabs)
__device__ float g_partred[8 * NN];           // stage-2 reduced partials (8 groups)
__device__ float g_ttpart[GRIDF];             // per-CTA sum of t_r^2 (= p.Ap partials)
__device__ float g_b[NN], g_r[NN], g_p[NN], g_v[NN], g_qh[NN];
__device__ float g_rs[NITER + 2];
__device__ float g_mpart[64 * 8];
__device__ float g_fftsum[8];

// ---------------------------------------------------------------------------
// Fused normal-equations operator, software-pipelined:
// ONE pass over H computes per-CTA partials of Ap = H^T(Hp) and tt = ||Hp||^2.
// Next row's loads are issued BEFORE the block reduce of the current row so
// DRAM loads stay in flight across the __syncthreads.
// ---------------------------------------------------------------------------
__global__ __launch_bounds__(256, 2) void normal_fused_kernel(const float* __restrict__ H) {
    __shared__ float4 psh[2048];     // p, 32 KB
    __shared__ float sw[2][8];
    int tid = threadIdx.x;
    const float4* p4 = reinterpret_cast<const float4*>(g_p);
    for (int i = tid; i < 2048; i += 256) psh[i] = p4[i];
    __syncthreads();

    int bid = blockIdx.x;
    int row0, nrows;
    if (bid < 200) { row0 = bid * 28; nrows = 28; }
    else           { row0 = 5600 + (bid - 200) * 27; nrows = 27; }

    const float4* hrow = reinterpret_cast<const float4*>(H) + (size_t)row0 * 2048;

    float4 apa[8];
#pragma unroll
    for (int i = 0; i < 8; i++) apa[i] = make_float4(0.f, 0.f, 0.f, 0.f);
    float tta = 0.f;

    float4 cur[8];
#pragma unroll
    for (int i = 0; i < 8; i++) cur[i] = hrow[tid + i * 256];

    for (int r = 0; r < nrows; r++) {
        // issue next row's loads first (stay in flight across the barrier)
        float4 nxt[8];
        if (r + 1 < nrows) {
            const float4* h2 = hrow + (size_t)(r + 1) * 2048;
#pragma unroll
            for (int i = 0; i < 8; i++) nxt[i] = h2[tid + i * 256];
        }
        // dot(cur, p)
        float d = 0.f;
#pragma unroll
        for (int i = 0; i < 8; i++) {
            float4 pp = psh[tid + i * 256];
            d += cur[i].x * pp.x + cur[i].y * pp.y + cur[i].z * pp.z + cur[i].w * pp.w;
        }
        for (int o = 16; o; o >>= 1) d += __shfl_xor_sync(0xffffffffu, d, o);
        int buf = r & 1;
        if ((tid & 31) == 0) sw[buf][tid >> 5] = d;
        __syncthreads();
        float tr = sw[buf][0] + sw[buf][1] + sw[buf][2] + sw[buf][3]
                 + sw[buf][4] + sw[buf][5] + sw[buf][6] + sw[buf][7];
        if (tid == 0) tta += tr * tr;
#pragma unroll
        for (int i = 0; i < 8; i++) {
            apa[i].x += tr * cur[i].x; apa[i].y += tr * cur[i].y;
            apa[i].z += tr * cur[i].z; apa[i].w += tr * cur[i].w;
        }
        if (r + 1 < nrows) {
#pragma unroll
            for (int i = 0; i < 8; i++) cur[i] = nxt[i];
        }
    }
    float4* slab4 = reinterpret_cast<float4*>(g_slab) + (size_t)bid * 2048;
#pragma unroll
    for (int i = 0; i < 8; i++) slab4[tid + i * 256] = apa[i];
    if (tid == 0) g_ttpart[bid] = tta;
}

// stage-2 slab reduce: 296 slabs -> 8 group partials. grid (8 colblocks, 8 groups)
__global__ __launch_bounds__(256) void reduce_slab_kernel() {
    int j = blockIdx.x * 256 + threadIdx.x;       // float4 column (0..2047)
    int g = blockIdx.y;                           // group 0..7 (37 slabs each)
    const float4* s4 = reinterpret_cast<const float4*>(g_slab);
    float4 acc = make_float4(0.f, 0.f, 0.f, 0.f);
    int c0 = g * 37;
#pragma unroll 4
    for (int c = 0; c < 37; c++) {
        float4 v = s4[(size_t)(c0 + c) * 2048 + j];
        acc.x += v.x; acc.y += v.y; acc.z += v.z; acc.w += v.w;
    }
    reinterpret_cast<float4*>(g_partred)[(size_t)g * 2048 + j] = acc;
}

// ---------------------------------------------------------------------------
// qh = H v : one block per row (final pass only)
// ---------------------------------------------------------------------------
__global__ __launch_bounds__(256) void gemv_n_kernel(const float* __restrict__ H) {
    int row = blockIdx.x;
    const float4* h4 = reinterpret_cast<const float4*>(H + (size_t)row * NN);
    const float4* x4 = reinterpret_cast<const float4*>(g_v);
    float acc = 0.f;
#pragma unroll
    for (int i = 0; i < 8; i++) {
        int idx = threadIdx.x + i * 256;
        float4 a = h4[idx], b = x4[idx];
        acc += a.x * b.x + a.y * b.y + a.z * b.z + a.w * b.w;
    }
    for (int o = 16; o; o >>= 1) acc += __shfl_down_sync(0xffffffffu, acc, o);
    __shared__ float sh[8];
    if ((threadIdx.x & 31) == 0) sh[threadIdx.x >> 5] = acc;
    __syncthreads();
    if (threadIdx.x == 0) {
        g_qh[row] = sh[0] + sh[1] + sh[2] + sh[3] + sh[4] + sh[5] + sh[6] + sh[7];
    }
}

// setup: partial column sums of b = H^T x. grid (8 colchunks, 64 rowchunks).
__global__ __launch_bounds__(256) void gemv_t_partial_kernel(
    const float* __restrict__ H, const float* __restrict__ xin) {
    int col4 = blockIdx.x * 256 + threadIdx.x;
    int row0 = blockIdx.y * 128;
    __shared__ float xs[128];
    if (threadIdx.x < 128) xs[threadIdx.x] = xin[row0 + threadIdx.x];
    __syncthreads();
    const float4* Hp = reinterpret_cast<const float4*>(H) + (size_t)row0 * 2048 + col4;
    float4 acc = make_float4(0.f, 0.f, 0.f, 0.f);
#pragma unroll 4
    for (int r = 0; r < 128; r++) {
        float4 h = Hp[(size_t)r * 2048];
        float s = xs[r];
        acc.x += h.x * s; acc.y += h.y * s; acc.z += h.z * s; acc.w += h.w * s;
    }
    reinterpret_cast<float4*>(g_slab)[(size_t)blockIdx.y * 2048 + col4] = acc;
}

// setup reduce: 64 slabs -> g_b
__global__ __launch_bounds__(256) void reduce_b64_kernel() {
    int j = blockIdx.x * 256 + threadIdx.x;
    const float4* part = reinterpret_cast<const float4*>(g_slab);
    float4 acc = make_float4(0.f, 0.f, 0.f, 0.f);
#pragma unroll
    for (int c = 0; c < 64; c++) {
        float4 v = part[(size_t)c * 2048 + j];
        acc.x += v.x; acc.y += v.y; acc.z += v.z; acc.w += v.w;
    }
    reinterpret_cast<float4*>(g_b)[j] = acc;
}

// ---- block-wide fp32 sum helper (1024 threads) ----
__device__ __forceinline__ float block_sum_1024(float v, float* sh32) {
    for (int o = 16; o; o >>= 1) v += __shfl_down_sync(0xffffffffu, v, o);
    if ((threadIdx.x & 31) == 0) sh32[threadIdx.x >> 5] = v;
    __syncthreads();
    float s = 0.f;
    if (threadIdx.x == 0) {
#pragma unroll
        for (int i = 0; i < 32; i++) s += sh32[i];
        sh32[0] = s;
    }
    __syncthreads();
    s = sh32[0];
    __syncthreads();
    return s;
}

// v=0 ; r=p=b ; rs0 = b.b   (single block, 1024 threads)
__global__ __launch_bounds__(1024) void init_fused_kernel() {
    __shared__ float sh32[32];
    float part = 0.f;
#pragma unroll
    for (int i = 0; i < 2; i++) {
        int j = threadIdx.x + i * 1024;
        float4 b = reinterpret_cast<const float4*>(g_b)[j];
        reinterpret_cast<float4*>(g_r)[j] = b;
        reinterpret_cast<float4*>(g_p)[j] = b;
        reinterpret_cast<float4*>(g_v)[j] = make_float4(0.f, 0.f, 0.f, 0.f);
        part += b.x * b.x + b.y * b.y + b.z * b.z + b.w * b.w;
    }
    float rs = block_sum_1024(part, sh32);
    if (threadIdx.x == 0) g_rs[0] = rs;
}

// Fused CG step: tt = sum ttpart ; alpha = rs/(tt+eps) ; Ap from 8 group
// partials ; v += alpha p ; r -= alpha Ap ; rsn=||r||^2 ; beta ; p = r+beta p
__global__ __launch_bounds__(1024) void cg_fused_kernel(int it) {
    __shared__ float sh32[32];
    float ttp = 0.f;
    for (int i = threadIdx.x; i < GRIDF; i += 1024) ttp += g_ttpart[i];
    float tt = block_sum_1024(ttp, sh32);
    float rs = g_rs[it];
    float alpha = rs / (tt + EPSF);

    const float4* pr4 = reinterpret_cast<const float4*>(g_partred);
    float4 preg[2], rreg[2];
    float rsp = 0.f;
#pragma unroll
    for (int i = 0; i < 2; i++) {
        int j = threadIdx.x + i * 1024;
        float4 ap = make_float4(0.f, 0.f, 0.f, 0.f);
#pragma unroll
        for (int g = 0; g < 8; g++) {
            float4 v = pr4[(size_t)g * 2048 + j];
            ap.x += v.x; ap.y += v.y; ap.z += v.z; ap.w += v.w;
        }
        float4 p = reinterpret_cast<const float4*>(g_p)[j];
        float4 r = reinterpret_cast<const float4*>(g_r)[j];
        float4 v = reinterpret_cast<const float4*>(g_v)[j];
        v.x += alpha * p.x; v.y += alpha * p.y; v.z += alpha * p.z; v.w += alpha * p.w;
        r.x -= alpha * ap.x; r.y -= alpha * ap.y; r.z -= alpha * ap.z; r.w -= alpha * ap.w;
        reinterpret_cast<float4*>(g_v)[j] = v;
        reinterpret_cast<float4*>(g_r)[j] = r;
        preg[i] = p; rreg[i] = r;
        rsp += r.x * r.x + r.y * r.y + r.z * r.z + r.w * r.w;
    }
    float rsn = block_sum_1024(rsp, sh32);
    float beta = rsn / (rs + EPSF);
#pragma unroll
    for (int i = 0; i < 2; i++) {
        int j = threadIdx.x + i * 1024;
        float4 p = preg[i], r = rreg[i];
        p.x = r.x + beta * p.x; p.y = r.y + beta * p.y;
        p.z = r.z + beta * p.z; p.w = r.w + beta * p.w;
        reinterpret_cast<float4*>(g_p)[j] = p;
    }
    if (threadIdx.x == 0) g_rs[it + 1] = rsn;
}

// time-domain metric partials:
// s0=sum(qh-x)^2 s1=sum|qh-qt| s2=sum(qh-qt)^2 s3=sum qt^2
// s4=sum|v-vt|   s5=sum(v-vt)^2 s6=sum vt^2
__global__ void metrics_partial_kernel(const float* __restrict__ x,
                                       const float* __restrict__ qt,
                                       const float* __restrict__ vt) {
    int j = blockIdx.x * 128 + threadIdx.x;
    float qh = g_qh[j], vv = g_v[j];
    float qtj = qt[j], vtj = vt[j];
    float d0 = qh - x[j];
    float d1 = qh - qtj;
    float d2 = vv - vtj;
    float vals[7] = { d0 * d0, fabsf(d1), d1 * d1, qtj * qtj,
                      fabsf(d2), d2 * d2, vtj * vtj };
    __shared__ float sh4[4];
#pragma unroll
    for (int s = 0; s < 7; s++) {
        float d = vals[s];
        for (int o = 16; o; o >>= 1) d += __shfl_down_sync(0xffffffffu, d, o);
        if ((threadIdx.x & 31) == 0) sh4[threadIdx.x >> 5] = d;
        __syncthreads();
        if (threadIdx.x == 0)
            g_mpart[blockIdx.x * 8 + s] = sh4[0] + sh4[1] + sh4[2] + sh4[3];
        __syncthreads();
    }
}

// 8192-pt real FFT via 4096-pt complex FFT (pack even/odd), per block.
// mode 0: qh - qt ; 1: qt ; 2: v - vt ; 3: vt
__global__ void fft_metrics_kernel(const float* __restrict__ qt,
                                   const float* __restrict__ vt) {
    __shared__ float2 Z[4096];
    __shared__ float red[1024];
    int mode = blockIdx.x;
    int tid = threadIdx.x;

    for (int n = tid; n < 4096; n += 1024) {
        int i0 = 2 * n, i1 = 2 * n + 1;
        float a, b;
        if (mode == 0)      { a = g_qh[i0] - qt[i0]; b = g_qh[i1] - qt[i1]; }
        else if (mode == 1) { a = qt[i0];            b = qt[i1]; }
        else if (mode == 2) { a = g_v[i0] - vt[i0];  b = g_v[i1] - vt[i1]; }
        else                { a = vt[i0];            b = vt[i1]; }
        int r = (int)(__brev((unsigned)n) >> 20);  // 12-bit reversal
        Z[r] = make_float2(a, b);
    }
    __syncthreads();

    for (int half = 1; half < 4096; half <<= 1) {
        for (int i = tid; i < 2048; i += 1024) {
            int pos = i & (half - 1);
            int idx1 = ((i ^ pos) << 1) | pos;
            int idx2 = idx1 + half;
            float s, c;
            sincospif((float)pos / (float)half, &s, &c);  // w = c - i s
            float2 z2 = Z[idx2];
            float2 t = make_float2(c * z2.x + s * z2.y, c * z2.y - s * z2.x);
            float2 z1 = Z[idx1];
            Z[idx2] = make_float2(z1.x - t.x, z1.y - t.y);
            Z[idx1] = make_float2(z1.x + t.x, z1.y + t.y);
        }
        __syncthreads();
    }

    float sabs = 0.f, ssq = 0.f;
    for (int k = tid; k <= 4096; k += 1024) {
        float2 Zk = Z[k & 4095];
        float2 Zm = Z[(4096 - k) & 4095];
        float2 Zmc = make_float2(Zm.x, -Zm.y);
        float2 Fe = make_float2(0.5f * (Zk.x + Zmc.x), 0.5f * (Zk.y + Zmc.y));
        float2 Fd = make_float2(Zk.x - Zmc.x, Zk.y - Zmc.y);
        float2 Fo = make_float2(0.5f * Fd.y, -0.5f * Fd.x);  // -i/2 * Fd
        float s, c;
        sincospif((float)k / 4096.0f, &s, &c);  // e^{-i*2pi*k/8192}
        float Xr = Fe.x + (c * Fo.x + s * Fo.y);
        float Xi = Fe.y + (c * Fo.y - s * Fo.x);
        float m2 = Xr * Xr + Xi * Xi;
        sabs += sqrtf(m2);
        ssq += m2;
    }
    red[tid] = sabs;
    __syncthreads();
    for (int s = 512; s > 0; s >>= 1) {
        if (tid < s) red[tid] += red[tid + s];
        __syncthreads();
    }
    if (tid == 0) g_fftsum[2 * mode] = red[0];
    __syncthreads();
    red[tid] = ssq;
    __syncthreads();
    for (int s = 512; s > 0; s >>= 1) {
        if (tid < s) red[tid] += red[tid + s];
        __syncthreads();
    }
    if (tid == 0) g_fftsum[2 * mode + 1] = red[0];
}

__global__ void finalize_kernel(float* __restrict__ out, int out_size) {
    if (threadIdx.x != 0 || blockIdx.x != 0) return;
    float s[7];
    for (int k = 0; k < 7; k++) {
        float a = 0.f;
        for (int b = 0; b < 64; b++) a += g_mpart[b * 8 + k];
        s[k] = a;
    }
    float res[11];
    res[0]  = sqrtf(s[0]);                        // residual
    res[1]  = s[1] / (float)NN;                   // mae_target
    res[2]  = s[2] / (s[3] + EPSF);               // ce_target
    res[3]  = s[4] / (float)NN;                   // mae
    res[4]  = s[5] / (s[6] + EPSF);               // ce
    res[5]  = s[2] / (float)NN;                   // mse_v_t_target
    res[6]  = s[5] / (float)NN;                   // mse_v_t
    res[7]  = g_fftsum[0] / 4097.0f;              // mae_target_f
    res[8]  = g_fftsum[1] / (g_fftsum[3] + EPSF); // ce_target_f
    res[9]  = g_fftsum[4] / 4097.0f;              // mae_f
    res[10] = g_fftsum[5] / (g_fftsum[7] + EPSF); // ce_f
    for (int k = 0; k < 11; k++)
        if (NN + k < out_size) out[NN + k] = res[k];
}

__global__ void copy_v_kernel(float* __restrict__ out, int out_size) {
    int j = blockIdx.x * 128 + threadIdx.x;
    if (j >= out_size) return;
    if (j < NN) out[j] = g_v[j];
    else if (j >= NN + 11) out[j] = 0.f;
}

extern "C" void kernel_launch(void* const* d_in, const int* in_sizes, int n_in,
                              void* d_out, int out_size) {
    const float* H = nullptr;
    const float* x = nullptr;
    const float* vt = nullptr;
    const float* qt = nullptr;
    int vecseen = 0;
    for (int i = 0; i < n_in; i++) {
        if (in_sizes[i] == NN * NN) {
            H = (const float*)d_in[i];
        } else if (in_sizes[i] == NN) {
            if (vecseen == 0)      x  = (const float*)d_in[i];
            else if (vecseen == 1) vt = (const float*)d_in[i];
            else if (vecseen == 2) qt = (const float*)d_in[i];
            vecseen++;
        }
    }
    float* out = (float*)d_out;

    // b = H^T x ; v=0 ; r=p=b ; rs0=b.b
    gemv_t_partial_kernel<<<dim3(8, 64), 256>>>(H, x);
    reduce_b64_kernel<<<8, 256>>>();
    init_fused_kernel<<<1, 1024>>>();

    for (int it = 0; it < NITER; it++) {
        normal_fused_kernel<<<GRIDF, 256>>>(H);       // one pipelined pass: Ap partials + tt
        reduce_slab_kernel<<<dim3(8, 8), 256>>>();    // 296 -> 8 group partials
        cg_fused_kernel<<<1, 1024>>>(it);             // scalars + vector updates
    }

    gemv_n_kernel<<<NN, 256>>>(H);                    // q_hat = H v
    metrics_partial_kernel<<<64, 128>>>(x, qt, vt);
    fft_metrics_kernel<<<4, 1024>>>(qt, vt);
    finalize_kernel<<<1, 32>>>(out, out_size);
    {
        int nblk = (out_size + 127) / 128;
        if (nblk < 1) nblk = 1;
        copy_v_kernel<<<nblk, 128>>>(out, out_size);
    }
}

// round 5
// speedup vs baseline: 1.6071x; 1.0665x over previous
#include <cuda_runtime.h>
#include <cstdint>
#include <math.h>

#define NN 8192
#define EPSF 1e-20f
#define NITER 32
#define NCTA 148
#define NTHR 512
#define ROWB 32768               // bytes per H row

// dynamic smem layout
#define SM_MBAR 0                // 4 mbarriers, 16B stride
#define SM_WRED 128              // 2 x 16 warp partials (double-buffered)
#define SM_GPART 1024            // 512 floats (phase-B group partials)
#define SM_SRED 3072             // 64 floats (phase-B rs partials)
#define SM_RING 4096             // 4 x 32768 row buffers
#define SMEM_TOTAL (SM_RING + 4 * ROWB)

// ---- device scratch (no allocations allowed) ----
__device__ float g_slab[NCTA * NN];     // 4.85 MB per-CTA Ap partial slabs
__device__ float g_ttpart[NCTA];
__device__ float g_rspart[NCTA];
__device__ float g_r[NN], g_p[NN], g_v[NN], g_qh[NN];
__device__ float g_mpart[64 * 8];
__device__ float g_fftsum[8];
__device__ unsigned g_flags[NCTA];      // grid-barrier flags (monotone across replays)

// ---------------- PTX helpers ----------------
__device__ __forceinline__ uint32_t sm_u32(const void* p) {
    uint32_t a;
    asm("{ .reg .u64 t; cvta.to.shared.u64 t, %1; cvt.u32.u64 %0, t; }" : "=r"(a) : "l"(p));
    return a;
}
#define MB_INIT(a, c) \
    asm volatile("mbarrier.init.shared.b64 [%0], %1;" :: "r"(a), "r"(c) : "memory")
#define MB_EXPECT(a, b) \
    asm volatile("mbarrier.arrive.expect_tx.shared.b64 _, [%0], %1;" :: "r"(a), "r"(b) : "memory")
#define BULK_LD(dst, src, sz, mb) \
    asm volatile("cp.async.bulk.shared::cta.global.mbarrier::complete_tx::bytes [%0], [%1], %2, [%3];" \
                 :: "r"(dst), "l"(src), "r"(sz), "r"(mb) : "memory")

__device__ __forceinline__ void mb_wait(uint32_t mbar, uint32_t parity) {
    uint32_t done;
    do {
        asm volatile("{ .reg .pred p; mbarrier.try_wait.parity.acquire.cta.shared::cta.b64 p, [%1], %2; "
                     "selp.b32 %0, 1, 0, p; }" : "=r"(done) : "r"(mbar), "r"(parity) : "memory");
    } while (!done);
}

__device__ __forceinline__ void grid_bar(int tid, int bid, unsigned gen) {
    __syncthreads();
    if (tid == 0)
        asm volatile("st.global.release.gpu.u32 [%0], %1;" :: "l"(&g_flags[bid]), "r"(gen) : "memory");
    if (tid < NCTA) {
        unsigned v;
        do {
            asm volatile("ld.global.acquire.gpu.u32 %0, [%1];" : "=r"(v) : "l"(&g_flags[tid]) : "memory");
        } while ((int)(v - gen) < 0);
    }
    __syncthreads();
}

// ---------------------------------------------------------------------------
// One streaming pass over this CTA's rows via TMA ring.
// MODE 0: tr = dot(row, preg)   -> apa += tr*row, ta += tr*tr   (CG matvec)
// MODE 1: tr = xvec[row]        -> apa += tr*row                (setup b = H^T x)
// MODE 2: tr = dot(row, preg)   -> g_qh[row] = tr               (final q = H v)
// ---------------------------------------------------------------------------
template<int MODE>
__device__ __forceinline__ float run_pass(const float* __restrict__ H, char* smem,
                                          uint32_t smb, int tid, int row0, int nrows,
                                          unsigned& gq, const float4* preg, float4* apa,
                                          const float* __restrict__ xvec) {
    float* wred = (float*)(smem + SM_WRED);
    if (MODE != 2) {
#pragma unroll
        for (int c = 0; c < 4; c++) apa[c] = make_float4(0.f, 0.f, 0.f, 0.f);
    }
    float ta = 0.f;
    if (tid == 0) {
        int npro = nrows < 4 ? nrows : 4;
        for (int k = 0; k < npro; k++) {
            uint32_t slot = (gq + k) & 3;
            uint32_t mb = smb + SM_MBAR + slot * 16;
            MB_EXPECT(mb, ROWB);
            BULK_LD(smb + SM_RING + slot * ROWB,
                    (const void*)(H + (size_t)(row0 + k) * NN), (uint32_t)ROWB, mb);
        }
    }
    for (int r = 0; r < nrows; r++) {
        unsigned u = gq + r;
        uint32_t slot = u & 3;
        mb_wait(smb + SM_MBAR + slot * 16, (u >> 2) & 1);
        const float4* row4 = (const float4*)(smem + SM_RING + slot * ROWB);
        float4 st[4];
        float d = 0.f;
#pragma unroll
        for (int c = 0; c < 4; c++) {
            st[c] = row4[tid + NTHR * c];
            if (MODE != 1)
                d += st[c].x * preg[c].x + st[c].y * preg[c].y
                   + st[c].z * preg[c].z + st[c].w * preg[c].w;
        }
        float tr;
        if (MODE == 1) {
            tr = xvec[row0 + r];
            __syncthreads();            // all LDS of this slot done before reissue
        } else {
            for (int o = 16; o; o >>= 1) d += __shfl_xor_sync(0xffffffffu, d, o);
            if ((tid & 31) == 0) wred[(r & 1) * 16 + (tid >> 5)] = d;
            __syncthreads();
        }
        if (tid == 0 && r + 4 < nrows) {
            uint32_t mb = smb + SM_MBAR + slot * 16;  // slot (u+4)&3 == slot
            MB_EXPECT(mb, ROWB);
            BULK_LD(smb + SM_RING + slot * ROWB,
                    (const void*)(H + (size_t)(row0 + r + 4) * NN), (uint32_t)ROWB, mb);
        }
        if (MODE != 1) {
            tr = 0.f;
#pragma unroll
            for (int w = 0; w < 16; w++) tr += wred[(r & 1) * 16 + w];
        }
        if (MODE == 2) {
            if (tid == 0) g_qh[row0 + r] = tr;
        } else {
#pragma unroll
            for (int c = 0; c < 4; c++) {
                apa[c].x += tr * st[c].x; apa[c].y += tr * st[c].y;
                apa[c].z += tr * st[c].z; apa[c].w += tr * st[c].w;
            }
            ta += tr * tr;
        }
    }
    gq += (unsigned)nrows;
    return ta;
}

// phase B: slab reduce over own columns + vector update (or setup init)
__device__ __forceinline__ void phaseB(char* smem, int tid, int bid, int c0, int nc,
                                       float alpha, bool setup) {
    float* sgp = (float*)(smem + SM_GPART);
    float* sred = (float*)(smem + SM_SRED);
    int g = tid >> 6, tc = tid & 63;
    float part = 0.f;
    if (tc < nc) {
        for (int cs = g; cs < NCTA; cs += 8) part += g_slab[(size_t)cs * NN + c0 + tc];
    }
    sgp[g * 64 + tc] = part;
    __syncthreads();
    if (tid < nc) {
        float ap = 0.f;
#pragma unroll
        for (int gg = 0; gg < 8; gg++) ap += sgp[gg * 64 + tid];
        int j = c0 + tid;
        float rn;
        if (setup) {
            g_v[j] = 0.f;
            g_r[j] = ap;      // r = b
            rn = ap;
        } else {
            g_v[j] += alpha * g_p[j];
            rn = g_r[j] - alpha * ap;
            g_r[j] = rn;
        }
        sred[tid] = rn * rn;
    }
    __syncthreads();
    if (tid == 0) {
        float s = 0.f;
        for (int i = 0; i < nc; i++) s += sred[i];
        g_rspart[bid] = s;
    }
}

// ---------------------------------------------------------------------------
// The persistent CG kernel: setup + 32 iterations + final projection.
// ---------------------------------------------------------------------------
__global__ void __launch_bounds__(NTHR, 1) cgm_persistent(const float* __restrict__ H,
                                                          const float* __restrict__ x) {
    extern __shared__ char smem[];
    int tid = threadIdx.x, bid = blockIdx.x;
    uint32_t smb = sm_u32(smem);
    if (tid == 0) {
        for (int s = 0; s < 4; s++) MB_INIT(smb + SM_MBAR + s * 16, 1);
    }
    __syncthreads();
    unsigned base_gen = g_flags[bid];    // all slots equal at launch (monotone)
    unsigned barn = 0;
    unsigned gq = 0;

    int row0, nrows;
    if (bid < 52) { row0 = bid * 56; nrows = 56; }
    else          { row0 = 2912 + (bid - 52) * 55; nrows = 55; }
    int c0 = row0, nc = nrows;           // same partition for columns

    float4 apa[4], preg[4];
    float rs = 0.f;

    // ---- setup: b = H^T x (rank-1 streaming), then r=b, v=0, rs0 partials ----
    run_pass<1>(H, smem, smb, tid, row0, nrows, gq, preg, apa, x);
    {
        float4* slab4 = (float4*)(g_slab + (size_t)bid * NN);
#pragma unroll
        for (int c = 0; c < 4; c++) slab4[tid + NTHR * c] = apa[c];
    }
    grid_bar(tid, bid, base_gen + (++barn));
    phaseB(smem, tid, bid, c0, nc, 0.f, true);
    grid_bar(tid, bid, base_gen + (++barn));

    for (int it = 0; it < NITER; it++) {
        // ---- A: beta (redundant, fixed order), p update (registers + gmem) ----
        float rs_new = 0.f;
        for (int c = 0; c < NCTA; c++) rs_new += g_rspart[c];
        float beta = (it == 0) ? 0.f : rs_new / (rs + EPSF);
        rs = rs_new;
#pragma unroll
        for (int c = 0; c < 4; c++) {
            float4 rr = ((const float4*)g_r)[tid + NTHR * c];
            if (it == 0) preg[c] = rr;
            else preg[c] = make_float4(rr.x + beta * preg[c].x, rr.y + beta * preg[c].y,
                                       rr.z + beta * preg[c].z, rr.w + beta * preg[c].w);
            ((float4*)g_p)[tid + NTHR * c] = preg[c];
        }
        // ---- matvec: slab partials of H^T(Hp), tt partials ----
        float ta = run_pass<0>(H, smem, smb, tid, row0, nrows, gq, preg, apa, nullptr);
        {
            float4* slab4 = (float4*)(g_slab + (size_t)bid * NN);
#pragma unroll
            for (int c = 0; c < 4; c++) slab4[tid + NTHR * c] = apa[c];
        }
        if (tid == 0) g_ttpart[bid] = ta;
        grid_bar(tid, bid, base_gen + (++barn));

        // ---- B: alpha (redundant), Ap reduce + v,r update + rs partials ----
        float tt = 0.f;
        for (int c = 0; c < NCTA; c++) tt += g_ttpart[c];
        float alpha = rs / (tt + EPSF);
        phaseB(smem, tid, bid, c0, nc, alpha, false);
        grid_bar(tid, bid, base_gen + (++barn));
    }

    // ---- final: q_hat = H v ----
#pragma unroll
    for (int c = 0; c < 4; c++) preg[c] = ((const float4*)g_v)[tid + NTHR * c];
    run_pass<2>(H, smem, smb, tid, row0, nrows, gq, preg, apa, nullptr);
}

// ---------------------------------------------------------------------------
// metrics / fft / finalize / output (unchanged semantics)
// ---------------------------------------------------------------------------
__global__ void metrics_partial_kernel(const float* __restrict__ x,
                                       const float* __restrict__ qt,
                                       const float* __restrict__ vt) {
    int j = blockIdx.x * 128 + threadIdx.x;
    float qh = g_qh[j], vv = g_v[j];
    float qtj = qt[j], vtj = vt[j];
    float d0 = qh - x[j];
    float d1 = qh - qtj;
    float d2 = vv - vtj;
    float vals[7] = { d0 * d0, fabsf(d1), d1 * d1, qtj * qtj,
                      fabsf(d2), d2 * d2, vtj * vtj };
    __shared__ float sh4[4];
#pragma unroll
    for (int s = 0; s < 7; s++) {
        float d = vals[s];
        for (int o = 16; o; o >>= 1) d += __shfl_down_sync(0xffffffffu, d, o);
        if ((threadIdx.x & 31) == 0) sh4[threadIdx.x >> 5] = d;
        __syncthreads();
        if (threadIdx.x == 0)
            g_mpart[blockIdx.x * 8 + s] = sh4[0] + sh4[1] + sh4[2] + sh4[3];
        __syncthreads();
    }
}

__global__ void fft_metrics_kernel(const float* __restrict__ qt,
                                   const float* __restrict__ vt) {
    __shared__ float2 Z[4096];
    __shared__ float red[1024];
    int mode = blockIdx.x;
    int tid = threadIdx.x;

    for (int n = tid; n < 4096; n += 1024) {
        int i0 = 2 * n, i1 = 2 * n + 1;
        float a, b;
        if (mode == 0)      { a = g_qh[i0] - qt[i0]; b = g_qh[i1] - qt[i1]; }
        else if (mode == 1) { a = qt[i0];            b = qt[i1]; }
        else if (mode == 2) { a = g_v[i0] - vt[i0];  b = g_v[i1] - vt[i1]; }
        else                { a = vt[i0];            b = vt[i1]; }
        int r = (int)(__brev((unsigned)n) >> 20);
        Z[r] = make_float2(a, b);
    }
    __syncthreads();

    for (int half = 1; half < 4096; half <<= 1) {
        for (int i = tid; i < 2048; i += 1024) {
            int pos = i & (half - 1);
            int idx1 = ((i ^ pos) << 1) | pos;
            int idx2 = idx1 + half;
            float s, c;
            sincospif((float)pos / (float)half, &s, &c);
            float2 z2 = Z[idx2];
            float2 t = make_float2(c * z2.x + s * z2.y, c * z2.y - s * z2.x);
            float2 z1 = Z[idx1];
            Z[idx2] = make_float2(z1.x - t.x, z1.y - t.y);
            Z[idx1] = make_float2(z1.x + t.x, z1.y + t.y);
        }
        __syncthreads();
    }

    float sabs = 0.f, ssq = 0.f;
    for (int k = tid; k <= 4096; k += 1024) {
        float2 Zk = Z[k & 4095];
        float2 Zm = Z[(4096 - k) & 4095];
        float2 Zmc = make_float2(Zm.x, -Zm.y);
        float2 Fe = make_float2(0.5f * (Zk.x + Zmc.x), 0.5f * (Zk.y + Zmc.y));
        float2 Fd = make_float2(Zk.x - Zmc.x, Zk.y - Zmc.y);
        float2 Fo = make_float2(0.5f * Fd.y, -0.5f * Fd.x);
        float s, c;
        sincospif((float)k / 4096.0f, &s, &c);
        float Xr = Fe.x + (c * Fo.x + s * Fo.y);
        float Xi = Fe.y + (c * Fo.y - s * Fo.x);
        float m2 = Xr * Xr + Xi * Xi;
        sabs += sqrtf(m2);
        ssq += m2;
    }
    red[tid] = sabs;
    __syncthreads();
    for (int s = 512; s > 0; s >>= 1) {
        if (tid < s) red[tid] += red[tid + s];
        __syncthreads();
    }
    if (tid == 0) g_fftsum[2 * mode] = red[0];
    __syncthreads();
    red[tid] = ssq;
    __syncthreads();
    for (int s = 512; s > 0; s >>= 1) {
        if (tid < s) red[tid] += red[tid + s];
        __syncthreads();
    }
    if (tid == 0) g_fftsum[2 * mode + 1] = red[0];
}

__global__ void finalize_kernel(float* __restrict__ out, int out_size) {
    if (threadIdx.x != 0 || blockIdx.x != 0) return;
    float s[7];
    for (int k = 0; k < 7; k++) {
        float a = 0.f;
        for (int b = 0; b < 64; b++) a += g_mpart[b * 8 + k];
        s[k] = a;
    }
    float res[11];
    res[0]  = sqrtf(s[0]);
    res[1]  = s[1] / (float)NN;
    res[2]  = s[2] / (s[3] + EPSF);
    res[3]  = s[4] / (float)NN;
    res[4]  = s[5] / (s[6] + EPSF);
    res[5]  = s[2] / (float)NN;
    res[6]  = s[5] / (float)NN;
    res[7]  = g_fftsum[0] / 4097.0f;
    res[8]  = g_fftsum[1] / (g_fftsum[3] + EPSF);
    res[9]  = g_fftsum[4] / 4097.0f;
    res[10] = g_fftsum[5] / (g_fftsum[7] + EPSF);
    for (int k = 0; k < 11; k++)
        if (NN + k < out_size) out[NN + k] = res[k];
}

__global__ void copy_v_kernel(float* __restrict__ out, int out_size) {
    int j = blockIdx.x * 128 + threadIdx.x;
    if (j >= out_size) return;
    if (j < NN) out[j] = g_v[j];
    else if (j >= NN + 11) out[j] = 0.f;
}

extern "C" void kernel_launch(void* const* d_in, const int* in_sizes, int n_in,
                              void* d_out, int out_size) {
    const float* H = nullptr;
    const float* x = nullptr;
    const float* vt = nullptr;
    const float* qt = nullptr;
    int vecseen = 0;
    for (int i = 0; i < n_in; i++) {
        if (in_sizes[i] == NN * NN) {
            H = (const float*)d_in[i];
        } else if (in_sizes[i] == NN) {
            if (vecseen == 0)      x  = (const float*)d_in[i];
            else if (vecseen == 1) vt = (const float*)d_in[i];
            else if (vecseen == 2) qt = (const float*)d_in[i];
            vecseen++;
        }
    }
    float* out = (float*)d_out;

    cudaFuncSetAttribute(cgm_persistent, cudaFuncAttributeMaxDynamicSharedMemorySize,
                         SMEM_TOTAL);

    cgm_persistent<<<NCTA, NTHR, SMEM_TOTAL>>>(H, x);

    metrics_partial_kernel<<<64, 128>>>(x, qt, vt);
    fft_metrics_kernel<<<4, 1024>>>(qt, vt);
    finalize_kernel<<<1, 32>>>(out, out_size);
    {
        int nblk = (out_size + 127) / 128;
        if (nblk < 1) nblk = 1;
        copy_v_kernel<<<nblk, 128>>>(out, out_size);
    }
}